// round 1
// baseline (speedup 1.0000x reference)
#include <cuda_runtime.h>
#include <math.h>

#define NBINS    65536
#define K_MAX    16384
#define N_MAX    1048576
#define EPSF     1e-8f
#define LOG_BOUND -120.0f

// ---------------- device scratch (no allocations allowed) ----------------
__device__ unsigned int g_partial_max[1024];
__device__ float g_m;            // softmax max
__device__ float g_Z;            // softmax denominator
__device__ float g_sum_alloc;    // sum of allocation weighting
__device__ int   g_count;        // number of selected (small-usage) elements
__device__ int   g_thresh_bin;   // histogram threshold bin
__device__ float g_key_norm;
__device__ int   g_hist[NBINS];
__device__ float g_s[N_MAX];     // cosine*beta scores
__device__ float g_alloc[N_MAX]; // allocation weighting (sparse nonzero)
__device__ float g_buf_u[K_MAX];
__device__ float g_buf_lu[K_MAX];
__device__ int   g_buf_idx[K_MAX];

// orderable-uint encoding for float atomic max (handles negatives)
__device__ __forceinline__ unsigned int enc_f(float f) {
    unsigned int u = __float_as_uint(f);
    return (u & 0x80000000u) ? ~u : (u | 0x80000000u);
}
__device__ __forceinline__ float dec_f(unsigned int u) {
    return (u & 0x80000000u) ? __uint_as_float(u & 0x7FFFFFFFu)
                             : __uint_as_float(~u);
}

// ---------------- kernel 0: init scratch + key norm ----------------
__global__ void k_init(const float* __restrict__ key) {
    int i = blockIdx.x * blockDim.x + threadIdx.x;
    int stride = gridDim.x * blockDim.x;
    for (int b = i; b < NBINS; b += stride) g_hist[b] = 0;
    if (i < 1024) g_partial_max[i] = 0u;
    if (i == 0) {
        g_Z = 0.0f;
        g_sum_alloc = 0.0f;
        g_count = 0;
        g_thresh_bin = NBINS - 1;
    }
    if (blockIdx.x == 0) {
        __shared__ float sh[64];
        if (threadIdx.x < 64) {
            float k = key[threadIdx.x];
            sh[threadIdx.x] = k * k;
        }
        __syncthreads();
        if (threadIdx.x == 0) {
            float t = 0.0f;
            for (int j = 0; j < 64; j++) t += sh[j];
            g_key_norm = sqrtf(t);
        }
    }
}

// ---------------- kernel 1: main pass (warp per row, W=64) ----------------
__global__ void k_main(const float* __restrict__ mem,
                       const float* __restrict__ key,
                       const float* __restrict__ beta_p,
                       const float* __restrict__ fg,
                       const float* __restrict__ rw,
                       const float* __restrict__ pu,
                       const float* __restrict__ pw,
                       float* __restrict__ out_usage,
                       int N, int R) {
    __shared__ unsigned int smax[8];
    if (threadIdx.x < 8) smax[threadIdx.x] = 0u;
    __syncthreads();

    int tid = blockIdx.x * blockDim.x + threadIdx.x;
    int row = tid >> 5;
    int lane = tid & 31;
    bool act = row < N;

    float2 m2 = make_float2(0.f, 0.f);
    if (act) m2 = reinterpret_cast<const float2*>(mem)[row * 32 + lane];
    float2 k2 = reinterpret_cast<const float2*>(key)[lane];

    float dot = m2.x * k2.x + m2.y * k2.y;
    float sq  = m2.x * m2.x + m2.y * m2.y;
#pragma unroll
    for (int o = 16; o; o >>= 1) {
        dot += __shfl_xor_sync(0xFFFFFFFFu, dot, o);
        sq  += __shfl_xor_sync(0xFFFFFFFFu, sq, o);
    }

    if (act && lane == 0) {
        float norm = sqrtf(sq);
        float denom = fmaxf(norm, EPSF) * fmaxf(g_key_norm, EPSF);
        float beta = beta_p[0];
        float s = (dot / denom) * beta;
        g_s[row] = s;
        g_alloc[row] = 0.0f;

        float ret = 1.0f;
#pragma unroll 8
        for (int r = 0; r < R; r++)
            ret *= (1.0f - rw[row * R + r] * fg[r]);
        float a = pu[row], b = pw[row];
        float u_ = (a + b - a * b) * ret;
        out_usage[row] = u_;

        int bin = (int)(u_ * (float)NBINS);
        bin = max(0, min(bin, NBINS - 1));
        atomicAdd(&g_hist[bin], 1);

        smax[threadIdx.x >> 5] = enc_f(s);
    }
    __syncthreads();
    if (threadIdx.x == 0) {
        unsigned int mx = 0u;
#pragma unroll
        for (int j = 0; j < 8; j++) mx = max(mx, smax[j]);
        atomicMax(&g_partial_max[blockIdx.x & 1023], mx);
    }
}

// ---------------- kernel 2: global max + threshold bin ----------------
__global__ void k_thresh() {
    __shared__ unsigned int sm[1024];
    __shared__ float spre[1024];
    int t = threadIdx.x;

    sm[t] = g_partial_max[t];
    __syncthreads();
    for (int o = 512; o; o >>= 1) {
        if (t < o) sm[t] = max(sm[t], sm[t + o]);
        __syncthreads();
    }
    if (t == 0) g_m = dec_f(sm[0]);

    // per-thread chunk of 64 bins: weighted log upper-bound sum
    const float inv = 1.0f / (float)NBINS;
    int base = t * 64;
    float local = 0.0f;
    for (int b = 0; b < 64; b++) {
        int c = g_hist[base + b];
        if (c) local += (float)c * logf((float)(base + b + 1) * inv);
    }
    spre[t] = local;
    __syncthreads();
    // inclusive Hillis-Steele scan
    for (int o = 1; o < 1024; o <<= 1) {
        float v = (t >= o) ? spre[t - o] : 0.0f;
        __syncthreads();
        spre[t] += v;
        __syncthreads();
    }
    float prefix = (t == 0) ? 0.0f : spre[t - 1];
    if (prefix <= LOG_BOUND) {
        atomicMin(&g_thresh_bin, base);
    } else {
        float run = prefix;
        for (int b = 0; b < 64; b++) {
            int c = g_hist[base + b];
            if (c) run += (float)c * logf((float)(base + b + 1) * inv);
            if (run <= LOG_BOUND) {
                atomicMin(&g_thresh_bin, base + b);
                break;
            }
        }
    }
}

// ---------------- kernel 3: softmax denominator + gather small-usage set ----
__global__ void k_gather(const float* __restrict__ usage, int N) {
    __shared__ float sh[256];
    int i = blockIdx.x * blockDim.x + threadIdx.x;
    float e = 0.0f;
    float m = g_m;
    int tb = g_thresh_bin;
    if (i < N) {
        e = expf(g_s[i] - m);
        float u_ = usage[i];
        int bin = (int)(u_ * (float)NBINS);
        bin = max(0, min(bin, NBINS - 1));
        if (bin <= tb) {
            int p = atomicAdd(&g_count, 1);
            if (p < K_MAX) {
                g_buf_u[p] = u_;
                g_buf_lu[p] = logf(u_);
                g_buf_idx[p] = i;
            }
        }
    }
    sh[threadIdx.x] = e;
    __syncthreads();
    for (int o = 128; o; o >>= 1) {
        if (threadIdx.x < o) sh[threadIdx.x] += sh[threadIdx.x + o];
        __syncthreads();
    }
    if (threadIdx.x == 0) atomicAdd(&g_Z, sh[0]);
}

// ---------------- kernel 4: allocation for selected head (warp / element) ----
__global__ void k_alloc() {
    int C = min(g_count, K_MAX);
    int w = (blockIdx.x * blockDim.x + threadIdx.x) >> 5;
    int lane = threadIdx.x & 31;
    if (w >= C) return;
    float ui = g_buf_u[w];
    int ii = g_buf_idx[w];
    float S = 0.0f;
    for (int j = lane; j < C; j += 32) {
        float uj = g_buf_u[j];
        bool before = (uj < ui) || (uj == ui && g_buf_idx[j] < ii);
        if (before) S += g_buf_lu[j];
    }
#pragma unroll
    for (int o = 16; o; o >>= 1) S += __shfl_xor_sync(0xFFFFFFFFu, S, o);
    if (lane == 0) {
        float a = (1.0f - ui) * expf(S);
        g_alloc[ii] = a;
        atomicAdd(&g_sum_alloc, a);
    }
}

// ---------------- kernel 5: finalize ww + precedence ----------------
__global__ void k_final(const float* __restrict__ prec,
                        const float* __restrict__ ag_p,
                        const float* __restrict__ wg_p,
                        float* __restrict__ out, int N) {
    int i = blockIdx.x * blockDim.x + threadIdx.x;
    if (i >= N) return;
    float Z = g_Z;
    float m = g_m;
    float ag = ag_p[0];
    float wg = wg_p[0];
    float content = expf(g_s[i] - m) / Z;
    float ww = wg * (ag * g_alloc[i] + (1.0f - ag) * content);
    float sum_ww = wg * (ag * g_sum_alloc + (1.0f - ag) * 1.0f);
    out[i] = ww;
    out[2 * N + i] = (1.0f - sum_ww) * prec[i] + ww;
}

// ---------------- launcher ----------------
extern "C" void kernel_launch(void* const* d_in, const int* in_sizes, int n_in,
                              void* d_out, int out_size) {
    const float* mem  = (const float*)d_in[0];
    const float* key  = (const float*)d_in[1];
    const float* beta = (const float*)d_in[2];
    const float* fg   = (const float*)d_in[3];
    const float* rw   = (const float*)d_in[4];
    const float* pu   = (const float*)d_in[5];
    const float* pw   = (const float*)d_in[6];
    const float* ag   = (const float*)d_in[7];
    const float* wg   = (const float*)d_in[8];
    const float* prec = (const float*)d_in[9];

    int N = in_sizes[0] / 64;   // W = 64
    int R = in_sizes[3];        // = 8

    float* out = (float*)d_out;
    float* out_usage = out + N; // outputs: [ww | usage | new_precedence]

    k_init<<<256, 256>>>(key);
    k_main<<<(N + 7) / 8, 256>>>(mem, key, beta, fg, rw, pu, pw, out_usage, N, R);
    k_thresh<<<1, 1024>>>();
    k_gather<<<(N + 255) / 256, 256>>>(out_usage, N);
    k_alloc<<<K_MAX / 32, 1024>>>();
    k_final<<<(N + 255) / 256, 256>>>(prec, ag, wg, out, N);
}

// round 3
// speedup vs baseline: 1.7875x; 1.7875x over previous
#include <cuda_runtime.h>
#include <math.h>

#define NBINS    8192
#define K_MAX    16384
#define N_MAX    1048576
#define EPSF     1e-8f
#define LOG_BOUND -120.0f

// ---------------- device scratch (no allocations allowed) ----------------
__device__ unsigned int g_partial_max[1024];
__device__ float g_m;            // softmax max
__device__ float g_Z;            // softmax denominator
__device__ float g_sum_alloc;    // sum of allocation weighting
__device__ int   g_count;        // number of selected (small-usage) elements
__device__ int   g_thresh_bin;   // histogram threshold bin
__device__ float g_key_norm;
__device__ int   g_hist[NBINS];
__device__ float g_s[N_MAX];     // cosine*beta scores
__device__ float g_buf_u[K_MAX];
__device__ float g_buf_lu[K_MAX];
__device__ float g_buf_a[K_MAX];
__device__ int   g_buf_idx[K_MAX];

// orderable-uint encoding for float atomic max (handles negatives)
__device__ __forceinline__ unsigned int enc_f(float f) {
    unsigned int u = __float_as_uint(f);
    return (u & 0x80000000u) ? ~u : (u | 0x80000000u);
}
__device__ __forceinline__ float dec_f(unsigned int u) {
    return (u & 0x80000000u) ? __uint_as_float(u & 0x7FFFFFFFu)
                             : __uint_as_float(~u);
}

// ---------------- kernel 0: init scratch + key norm ----------------
__global__ void k_init(const float* __restrict__ key) {
    int i = blockIdx.x * blockDim.x + threadIdx.x;
    int stride = gridDim.x * blockDim.x;
    for (int b = i; b < NBINS; b += stride) g_hist[b] = 0;
    for (int b = i; b < 1024; b += stride) g_partial_max[b] = 0u;
    if (i == 0) {
        g_Z = 0.0f;
        g_sum_alloc = 0.0f;
        g_count = 0;
        g_thresh_bin = NBINS - 1;
    }
    if (blockIdx.x == 0) {
        __shared__ float sh[64];
        if (threadIdx.x < 64) {
            float k = key[threadIdx.x];
            sh[threadIdx.x] = k * k;
        }
        __syncthreads();
        if (threadIdx.x == 0) {
            float t = 0.0f;
            for (int j = 0; j < 64; j++) t += sh[j];
            g_key_norm = sqrtf(t);
        }
    }
}

// ---------------- kernel 1: main pass (2 rows per warp, float4 loads) -------
__global__ void k_main(const float4* __restrict__ mem4,
                       const float4* __restrict__ key4,
                       const float* __restrict__ beta_p,
                       const float* __restrict__ fg,
                       const float* __restrict__ rw,
                       const float* __restrict__ pu,
                       const float* __restrict__ pw,
                       float* __restrict__ out_usage,
                       int N) {
    __shared__ unsigned int smax[8];
    int lane = threadIdx.x & 31;
    int wid  = threadIdx.x >> 5;
    if (lane == 0) smax[wid] = 0u;
    __syncthreads();

    int warp = (blockIdx.x * blockDim.x + threadIdx.x) >> 5;
    int sub  = lane >> 4;          // 0 or 1: which of the 2 rows
    int l16  = lane & 15;
    int row  = warp * 2 + sub;
    bool act = row < N;

    float4 k4 = key4[l16];
    float4 m4 = make_float4(0.f, 0.f, 0.f, 0.f);
    if (act) m4 = mem4[row * 16 + l16];

    float dot = m4.x * k4.x + m4.y * k4.y + m4.z * k4.z + m4.w * k4.w;
    float sq  = m4.x * m4.x + m4.y * m4.y + m4.z * m4.z + m4.w * m4.w;
#pragma unroll
    for (int o = 8; o; o >>= 1) {
        dot += __shfl_xor_sync(0xFFFFFFFFu, dot, o);
        sq  += __shfl_xor_sync(0xFFFFFFFFu, sq, o);
    }

    // retention: lanes l16 in [0,8) of each half handle one read-head each
    int l8 = lane & 7;
    float p = 1.0f;
    if (act && l16 < 8) p = 1.0f - rw[row * 8 + l8] * fg[l8];
#pragma unroll
    for (int o = 4; o; o >>= 1) p *= __shfl_xor_sync(0xFFFFFFFFu, p, o);

    unsigned int enc = 0u;
    if (act && l16 == 0) {
        float norm = sqrtf(sq);
        float denom = fmaxf(norm, EPSF) * fmaxf(g_key_norm, EPSF);
        float s = (dot / denom) * beta_p[0];
        g_s[row] = s;

        float a = pu[row], b = pw[row];
        float u_ = (a + b - a * b) * p;
        out_usage[row] = u_;

        int bin = (int)(u_ * (float)NBINS);
        bin = max(0, min(bin, NBINS - 1));
        atomicAdd(&g_hist[bin], 1);

        enc = enc_f(s);
    }
    // combine the two row-results of this warp (lanes 0 and 16)
    enc = max(enc, __shfl_xor_sync(0xFFFFFFFFu, enc, 16));
    if (lane == 0) smax[wid] = enc;
    __syncthreads();
    if (threadIdx.x == 0) {
        unsigned int mx = 0u;
#pragma unroll
        for (int j = 0; j < 8; j++) mx = max(mx, smax[j]);
        atomicMax(&g_partial_max[blockIdx.x & 1023], mx);
    }
}

// ---------------- kernel 2: global max + threshold bin ----------------
__global__ void k_thresh() {
    __shared__ unsigned int sm[1024];
    __shared__ float spre[1024];
    int t = threadIdx.x;

    sm[t] = g_partial_max[t];
    __syncthreads();
    for (int o = 512; o; o >>= 1) {
        if (t < o) sm[t] = max(sm[t], sm[t + o]);
        __syncthreads();
    }
    if (t == 0) g_m = dec_f(sm[0]);

    // per-thread chunk of 8 bins: weighted log-upper-bound sum
    const float inv = 1.0f / (float)NBINS;
    const int BPT = NBINS / 1024;       // 8
    int base = t * BPT;
    int cnt[BPT];
    float local = 0.0f;
#pragma unroll
    for (int b = 0; b < BPT; b++) {
        cnt[b] = g_hist[base + b];
        if (cnt[b]) local += (float)cnt[b] * __logf((float)(base + b + 1) * inv);
    }
    spre[t] = local;
    __syncthreads();
    // inclusive Hillis-Steele scan
    for (int o = 1; o < 1024; o <<= 1) {
        float v = (t >= o) ? spre[t - o] : 0.0f;
        __syncthreads();
        spre[t] += v;
        __syncthreads();
    }
    float prefix = (t == 0) ? 0.0f : spre[t - 1];
    if (prefix <= LOG_BOUND) {
        atomicMin(&g_thresh_bin, base);
    } else {
        float run = prefix;
#pragma unroll
        for (int b = 0; b < BPT; b++) {
            if (cnt[b]) run += (float)cnt[b] * __logf((float)(base + b + 1) * inv);
            if (run <= LOG_BOUND) {
                atomicMin(&g_thresh_bin, base + b);
                break;
            }
        }
    }
}

// ---------------- kernel 3: softmax denominator + gather small-usage set ----
__global__ void k_gather(const float4* __restrict__ usage4, int N4) {
    __shared__ float sh[8];
    int i = blockIdx.x * blockDim.x + threadIdx.x;
    int lane = threadIdx.x & 31;
    int wid  = threadIdx.x >> 5;
    float e = 0.0f;
    float m = g_m;
    int tb = g_thresh_bin;
    float ubound = (float)(tb + 1) / (float)NBINS;  // select u_ < ubound (bin<=tb)
    if (i < N4) {
        const float4 s4 = reinterpret_cast<const float4*>(g_s)[i];
        float4 u4 = usage4[i];
        e = expf(s4.x - m) + expf(s4.y - m) + expf(s4.z - m) + expf(s4.w - m);
        float uu[4] = {u4.x, u4.y, u4.z, u4.w};
#pragma unroll
        for (int c = 0; c < 4; c++) {
            int bin = (int)(uu[c] * (float)NBINS);
            bin = max(0, min(bin, NBINS - 1));
            if (bin <= tb) {
                int p = atomicAdd(&g_count, 1);
                if (p < K_MAX) {
                    g_buf_u[p] = uu[c];
                    g_buf_lu[p] = logf(uu[c]);
                    g_buf_idx[p] = i * 4 + c;
                }
            }
        }
    }
    (void)ubound;
#pragma unroll
    for (int o = 16; o; o >>= 1) e += __shfl_xor_sync(0xFFFFFFFFu, e, o);
    if (lane == 0) sh[wid] = e;
    __syncthreads();
    if (threadIdx.x == 0) {
        float t = 0.0f;
#pragma unroll
        for (int j = 0; j < 8; j++) t += sh[j];
        atomicAdd(&g_Z, t);
    }
}

// ---------------- kernel 4: allocation for selected head (warp / element) ----
__global__ void k_alloc() {
    int C = min(g_count, K_MAX);
    int w = (blockIdx.x * blockDim.x + threadIdx.x) >> 5;
    int lane = threadIdx.x & 31;
    if (w >= C) return;
    float ui = g_buf_u[w];
    int ii = g_buf_idx[w];
    float S = 0.0f;
    for (int j = lane; j < C; j += 32) {
        float uj = g_buf_u[j];
        bool before = (uj < ui) || (uj == ui && g_buf_idx[j] < ii);
        if (before) S += g_buf_lu[j];
    }
#pragma unroll
    for (int o = 16; o; o >>= 1) S += __shfl_xor_sync(0xFFFFFFFFu, S, o);
    if (lane == 0) {
        float a = (1.0f - ui) * expf(S);
        g_buf_a[w] = a;
        atomicAdd(&g_sum_alloc, a);
    }
}

// ---------------- kernel 5: finalize content part of ww + precedence --------
__global__ void k_final(const float4* __restrict__ prec4,
                        const float* __restrict__ ag_p,
                        const float* __restrict__ wg_p,
                        float* __restrict__ out, int N, int N4) {
    int i = blockIdx.x * blockDim.x + threadIdx.x;
    if (i >= N4) return;
    float invZ = 1.0f / g_Z;
    float m = g_m;
    float ag = ag_p[0];
    float wg = wg_p[0];
    float cw = wg * (1.0f - ag);
    float sum_ww = wg * (ag * g_sum_alloc + (1.0f - ag));
    float oms = 1.0f - sum_ww;

    float4 s4 = reinterpret_cast<const float4*>(g_s)[i];
    float4 p4 = prec4[i];
    float4 ww, np;
    ww.x = cw * expf(s4.x - m) * invZ;
    ww.y = cw * expf(s4.y - m) * invZ;
    ww.z = cw * expf(s4.z - m) * invZ;
    ww.w = cw * expf(s4.w - m) * invZ;
    np.x = oms * p4.x + ww.x;
    np.y = oms * p4.y + ww.y;
    np.z = oms * p4.z + ww.z;
    np.w = oms * p4.w + ww.w;
    reinterpret_cast<float4*>(out)[i] = ww;
    reinterpret_cast<float4*>(out + 2 * N)[i] = np;
}

// ---------------- kernel 6: scatter-add allocation contributions ------------
__global__ void k_apply(const float* __restrict__ ag_p,
                        const float* __restrict__ wg_p,
                        float* __restrict__ out, int N) {
    int C = min(g_count, K_MAX);
    int w = blockIdx.x * blockDim.x + threadIdx.x;
    if (w >= C) return;
    float val = wg_p[0] * ag_p[0] * g_buf_a[w];
    int ii = g_buf_idx[w];
    out[ii] += val;          // indices unique -> no atomics needed
    out[2 * N + ii] += val;
}

// ---------------- launcher ----------------
extern "C" void kernel_launch(void* const* d_in, const int* in_sizes, int n_in,
                              void* d_out, int out_size) {
    const float* mem  = (const float*)d_in[0];
    const float* key  = (const float*)d_in[1];
    const float* beta = (const float*)d_in[2];
    const float* fg   = (const float*)d_in[3];
    const float* rw   = (const float*)d_in[4];
    const float* pu   = (const float*)d_in[5];
    const float* pw   = (const float*)d_in[6];
    const float* ag   = (const float*)d_in[7];
    const float* wg   = (const float*)d_in[8];
    const float* prec = (const float*)d_in[9];

    int N = in_sizes[0] / 64;   // W = 64
    int N4 = N / 4;

    float* out = (float*)d_out;
    float* out_usage = out + N; // outputs: [ww | usage | new_precedence]

    k_init<<<64, 256>>>(key);
    // 2 rows per warp, 8 warps per block -> 16 rows/block
    k_main<<<(N + 15) / 16, 256>>>(
        (const float4*)mem, (const float4*)key, beta, fg, rw, pu, pw,
        out_usage, N);
    k_thresh<<<1, 1024>>>();
    k_gather<<<(N4 + 255) / 256, 256>>>((const float4*)out_usage, N4);
    k_alloc<<<512, 1024>>>();
    k_final<<<(N4 + 255) / 256, 256>>>((const float4*)prec, ag, wg, out, N, N4);
    k_apply<<<(K_MAX + 255) / 256, 256>>>(ag, wg, out, N);
}